// round 1
// baseline (speedup 1.0000x reference)
#include <cuda_runtime.h>
#include <math.h>

#define Bb   8
#define Ss   1024
#define Dd   768
#define Hh   12
#define HDh  64
#define DFF  3072
#define LL   6

// ---------------- scratch (static device globals; no cudaMalloc allowed) ----------------
__device__ float gX [Bb*Ss*Dd];          // activations
__device__ float gQ [Bb*Ss*Dd];
__device__ float gK [Bb*Ss*Dd];
__device__ float gV [Bb*Ss*Dd];
__device__ float gS [100663296];         // B*H*S*S attention scores (402 MB)
__device__ float gHb[Bb*Ss*Dd];          // h1 / h2
__device__ float gY1[Bb*Ss*Dd];
__device__ float gF [Bb*Ss*DFF];         // FFN hidden

// ---------------- block reductions (blockDim = 256) ----------------
__device__ __forceinline__ float blockReduceSum(float v) {
    __shared__ float red[32];
    #pragma unroll
    for (int o = 16; o > 0; o >>= 1) v += __shfl_xor_sync(0xffffffffu, v, o);
    int lane = threadIdx.x & 31, w = threadIdx.x >> 5;
    if (lane == 0) red[w] = v;
    __syncthreads();
    v = (threadIdx.x < 8) ? red[threadIdx.x] : 0.f;
    if (w == 0) {
        #pragma unroll
        for (int o = 4; o > 0; o >>= 1) v += __shfl_xor_sync(0xffffffffu, v, o);
        if (lane == 0) red[0] = v;
    }
    __syncthreads();
    float r = red[0];
    __syncthreads();
    return r;
}

__device__ __forceinline__ float blockReduceMax(float v) {
    __shared__ float red[32];
    #pragma unroll
    for (int o = 16; o > 0; o >>= 1) v = fmaxf(v, __shfl_xor_sync(0xffffffffu, v, o));
    int lane = threadIdx.x & 31, w = threadIdx.x >> 5;
    if (lane == 0) red[w] = v;
    __syncthreads();
    v = (threadIdx.x < 8) ? red[threadIdx.x] : -3.4e38f;
    if (w == 0) {
        #pragma unroll
        for (int o = 4; o > 0; o >>= 1) v = fmaxf(v, __shfl_xor_sync(0xffffffffu, v, o));
        if (lane == 0) red[0] = v;
    }
    __syncthreads();
    float r = red[0];
    __syncthreads();
    return r;
}

// ---------------- embedding + positional encoding ----------------
__global__ void embed_kernel(const int* __restrict__ ids, const float* __restrict__ emb,
                             const float* __restrict__ pe, float* __restrict__ x) {
    int i  = blockIdx.x * blockDim.x + threadIdx.x;     // over B*S*D
    int d  = i % Dd;
    int bs = i / Dd;
    int s  = bs % Ss;
    x[i] = emb[(size_t)ids[bs] * Dd + d] + pe[(size_t)s * Dd + d];
}

// ---------------- Y[M,N] = X[M,K] @ W[N,K]^T + bias, optional relu ----------------
template<bool RELU>
__global__ __launch_bounds__(256) void gemm_nt_bias(
    int M, int N, int K,
    const float* __restrict__ X, const float* __restrict__ W,
    const float* __restrict__ bias, float* __restrict__ Y)
{
    __shared__ float Xs[16][132];
    __shared__ float Ws[16][132];
    const int bm = blockIdx.y * 128, bn = blockIdx.x * 128;
    const int tid = threadIdx.x, tx = tid & 15, ty = tid >> 4;
    float acc[8][8] = {};
    const float* Xp = X + (size_t)bm * K;
    const float* Wp = W + (size_t)bn * K;

    for (int k0 = 0; k0 < K; k0 += 16) {
        #pragma unroll
        for (int i = 0; i < 2; i++) {
            int idx = tid + i * 256;
            int r = idx >> 2, c4 = (idx & 3) << 2;
            float4 a = *(const float4*)(Xp + (size_t)r * K + k0 + c4);
            Xs[c4 + 0][r] = a.x; Xs[c4 + 1][r] = a.y; Xs[c4 + 2][r] = a.z; Xs[c4 + 3][r] = a.w;
            float4 b = *(const float4*)(Wp + (size_t)r * K + k0 + c4);
            Ws[c4 + 0][r] = b.x; Ws[c4 + 1][r] = b.y; Ws[c4 + 2][r] = b.z; Ws[c4 + 3][r] = b.w;
        }
        __syncthreads();
        #pragma unroll
        for (int kk = 0; kk < 16; kk++) {
            float a[8], b[8];
            *(float4*)(a)     = *(float4*)&Xs[kk][ty * 8];
            *(float4*)(a + 4) = *(float4*)&Xs[kk][ty * 8 + 4];
            *(float4*)(b)     = *(float4*)&Ws[kk][tx * 8];
            *(float4*)(b + 4) = *(float4*)&Ws[kk][tx * 8 + 4];
            #pragma unroll
            for (int i = 0; i < 8; i++)
                #pragma unroll
                for (int j = 0; j < 8; j++)
                    acc[i][j] = fmaf(a[i], b[j], acc[i][j]);
        }
        __syncthreads();
    }

    #pragma unroll
    for (int i = 0; i < 8; i++) {
        int m = bm + ty * 8 + i;
        #pragma unroll
        for (int j = 0; j < 8; j++) {
            int n = bn + tx * 8 + j;
            float v = acc[i][j] + bias[n];
            if (RELU) v = fmaxf(v, 0.f);
            Y[(size_t)m * N + n] = v;
        }
    }
}

// ---------------- scores[b,h] = (Q[b,h] @ K[b,h]^T) / 8 ----------------
__global__ __launch_bounds__(256) void gemm_scores(
    const float* __restrict__ Qb, const float* __restrict__ Kb, float* __restrict__ Sb)
{
    __shared__ float Xs[16][132];
    __shared__ float Ws[16][132];
    const int bh = blockIdx.z;
    const float* Xp = Qb + (size_t)bh * Ss * HDh + (size_t)(blockIdx.y * 128) * HDh;
    const float* Wp = Kb + (size_t)bh * Ss * HDh + (size_t)(blockIdx.x * 128) * HDh;
    float* Y = Sb + (size_t)bh * Ss * Ss;
    const int tid = threadIdx.x, tx = tid & 15, ty = tid >> 4;
    float acc[8][8] = {};

    for (int k0 = 0; k0 < HDh; k0 += 16) {
        #pragma unroll
        for (int i = 0; i < 2; i++) {
            int idx = tid + i * 256;
            int r = idx >> 2, c4 = (idx & 3) << 2;
            float4 a = *(const float4*)(Xp + (size_t)r * HDh + k0 + c4);
            Xs[c4 + 0][r] = a.x; Xs[c4 + 1][r] = a.y; Xs[c4 + 2][r] = a.z; Xs[c4 + 3][r] = a.w;
            float4 b = *(const float4*)(Wp + (size_t)r * HDh + k0 + c4);
            Ws[c4 + 0][r] = b.x; Ws[c4 + 1][r] = b.y; Ws[c4 + 2][r] = b.z; Ws[c4 + 3][r] = b.w;
        }
        __syncthreads();
        #pragma unroll
        for (int kk = 0; kk < 16; kk++) {
            float a[8], b[8];
            *(float4*)(a)     = *(float4*)&Xs[kk][ty * 8];
            *(float4*)(a + 4) = *(float4*)&Xs[kk][ty * 8 + 4];
            *(float4*)(b)     = *(float4*)&Ws[kk][tx * 8];
            *(float4*)(b + 4) = *(float4*)&Ws[kk][tx * 8 + 4];
            #pragma unroll
            for (int i = 0; i < 8; i++)
                #pragma unroll
                for (int j = 0; j < 8; j++)
                    acc[i][j] = fmaf(a[i], b[j], acc[i][j]);
        }
        __syncthreads();
    }

    const float scale = 0.125f;  // 1/sqrt(64)
    #pragma unroll
    for (int i = 0; i < 8; i++) {
        int m = blockIdx.y * 128 + ty * 8 + i;
        #pragma unroll
        for (int j = 0; j < 8; j++) {
            int n = blockIdx.x * 128 + tx * 8 + j;
            Y[(size_t)m * Ss + n] = acc[i][j] * scale;
        }
    }
}

// ---------------- in-place row softmax over 1024 ----------------
__global__ __launch_bounds__(256) void softmax_kernel(float* __restrict__ Sb) {
    float* p = Sb + (size_t)blockIdx.x * Ss;
    float4 v = ((float4*)p)[threadIdx.x];
    float m = fmaxf(fmaxf(v.x, v.y), fmaxf(v.z, v.w));
    m = blockReduceMax(m);
    float e0 = __expf(v.x - m), e1 = __expf(v.y - m), e2 = __expf(v.z - m), e3 = __expf(v.w - m);
    float s = blockReduceSum(e0 + e1 + e2 + e3);
    float inv = 1.f / s;
    float4 o = {e0 * inv, e1 * inv, e2 * inv, e3 * inv};
    ((float4*)p)[threadIdx.x] = o;
}

// ---------------- O[b,h] = att[b,h] @ V[b,h], scattered to [B,S,D] head layout ----------------
__global__ __launch_bounds__(256) void gemm_av(
    const float* __restrict__ Sb, const float* __restrict__ Vb, float* __restrict__ Ob)
{
    __shared__ float As[16][132];
    __shared__ float Vs[16][64];
    const int bh = blockIdx.z;
    const int b = bh / Hh, h = bh % Hh;
    const float* A  = Sb + (size_t)bh * Ss * Ss;
    const float* Vp = Vb + (size_t)bh * Ss * HDh;
    float* O = Ob + (size_t)b * Ss * Dd + (size_t)h * HDh;
    const int tid = threadIdx.x, tx = tid & 15, ty = tid >> 4;
    const int bm = blockIdx.y * 128;
    float acc[8][4] = {};

    for (int k0 = 0; k0 < Ss; k0 += 16) {
        #pragma unroll
        for (int i = 0; i < 2; i++) {
            int idx = tid + i * 256;
            int r = idx >> 2, c4 = (idx & 3) << 2;
            float4 a = *(const float4*)(A + (size_t)(bm + r) * Ss + k0 + c4);
            As[c4 + 0][r] = a.x; As[c4 + 1][r] = a.y; As[c4 + 2][r] = a.z; As[c4 + 3][r] = a.w;
        }
        {
            int r = tid >> 4, c4 = (tid & 15) << 2;
            *(float4*)&Vs[r][c4] = *(const float4*)(Vp + (size_t)(k0 + r) * HDh + c4);
        }
        __syncthreads();
        #pragma unroll
        for (int kk = 0; kk < 16; kk++) {
            float a[8];
            *(float4*)(a)     = *(float4*)&As[kk][ty * 8];
            *(float4*)(a + 4) = *(float4*)&As[kk][ty * 8 + 4];
            float4 bv = *(float4*)&Vs[kk][tx * 4];
            #pragma unroll
            for (int i = 0; i < 8; i++) {
                acc[i][0] = fmaf(a[i], bv.x, acc[i][0]);
                acc[i][1] = fmaf(a[i], bv.y, acc[i][1]);
                acc[i][2] = fmaf(a[i], bv.z, acc[i][2]);
                acc[i][3] = fmaf(a[i], bv.w, acc[i][3]);
            }
        }
        __syncthreads();
    }

    #pragma unroll
    for (int i = 0; i < 8; i++) {
        int m = bm + ty * 8 + i;
        float4 o = {acc[i][0], acc[i][1], acc[i][2], acc[i][3]};
        *(float4*)(O + (size_t)m * Dd + tx * 4) = o;
    }
}

// ---------------- out = LayerNorm(x + h) * g + b  (row = 768) ----------------
__global__ __launch_bounds__(256) void add_ln_kernel(
    const float* __restrict__ x, const float* __restrict__ h,
    const float* __restrict__ g, const float* __restrict__ bias, float* __restrict__ out)
{
    const size_t row = blockIdx.x;
    const float* px = x + row * Dd;
    const float* ph = h + row * Dd;
    int t = threadIdx.x;
    float v[3];
    #pragma unroll
    for (int i = 0; i < 3; i++) v[i] = px[t + i * 256] + ph[t + i * 256];
    float mu = blockReduceSum(v[0] + v[1] + v[2]) * (1.f / Dd);
    float q = 0.f;
    #pragma unroll
    for (int i = 0; i < 3; i++) { float d = v[i] - mu; q += d * d; }
    float var = blockReduceSum(q) * (1.f / Dd);
    float inv = rsqrtf(var + 1e-5f);
    float* po = out + row * Dd;
    #pragma unroll
    for (int i = 0; i < 3; i++) {
        int c = t + i * 256;
        po[c] = (v[i] - mu) * inv * g[c] + bias[c];
    }
}

// ---------------- host launcher ----------------
extern "C" void kernel_launch(void* const* d_in, const int* in_sizes, int n_in,
                              void* d_out, int out_size) {
    const int*   ids  = (const int*)  d_in[0];
    const float* emb  = (const float*)d_in[1];
    const float* pe   = (const float*)d_in[2];
    const float* Wq   = (const float*)d_in[3];
    const float* bq   = (const float*)d_in[4];
    const float* Wk   = (const float*)d_in[5];
    const float* bk   = (const float*)d_in[6];
    const float* Wv   = (const float*)d_in[7];
    const float* bv   = (const float*)d_in[8];
    const float* W1   = (const float*)d_in[9];
    const float* b1   = (const float*)d_in[10];
    const float* W2   = (const float*)d_in[11];
    const float* b2   = (const float*)d_in[12];
    const float* ln1g = (const float*)d_in[13];
    const float* ln1b = (const float*)d_in[14];
    const float* ln2g = (const float*)d_in[15];
    const float* ln2b = (const float*)d_in[16];

    float *X, *Q, *K, *V, *Sb, *Hb, *Y1, *F;
    cudaGetSymbolAddress((void**)&X,  gX);
    cudaGetSymbolAddress((void**)&Q,  gQ);
    cudaGetSymbolAddress((void**)&K,  gK);
    cudaGetSymbolAddress((void**)&V,  gV);
    cudaGetSymbolAddress((void**)&Sb, gS);
    cudaGetSymbolAddress((void**)&Hb, gHb);
    cudaGetSymbolAddress((void**)&Y1, gY1);
    cudaGetSymbolAddress((void**)&F,  gF);

    const int M = Bb * Ss;                 // 8192

    embed_kernel<<<(Bb * Ss * Dd) / 256, 256>>>(ids, emb, pe, X);

    for (int l = 0; l < LL; l++) {
        const float* wq = Wq + (size_t)l * Dd * Dd;
        const float* wk = Wk + (size_t)l * Dd * Dd;
        const float* wv = Wv + (size_t)l * Dd * Dd;
        const float* w1 = W1 + (size_t)l * DFF * Dd;
        const float* w2 = W2 + (size_t)l * Dd * DFF;

        dim3 gQKV(Dd / 128, M / 128);      // (6, 64)
        gemm_nt_bias<false><<<gQKV, 256>>>(M, Dd, Dd, X, wq, bq + l * Dd, Q);
        gemm_nt_bias<false><<<gQKV, 256>>>(M, Dd, Dd, X, wk, bk + l * Dd, K);
        gemm_nt_bias<false><<<gQKV, 256>>>(M, Dd, Dd, X, wv, bv + l * Dd, V);

        gemm_scores<<<dim3(8, 8, Bb * Hh), 256>>>(Q, K, Sb);
        softmax_kernel<<<Bb * Hh * Ss, 256>>>(Sb);
        gemm_av<<<dim3(1, 8, Bb * Hh), 256>>>(Sb, V, Hb);

        add_ln_kernel<<<M, 256>>>(X, Hb, ln1g + l * Dd, ln1b + l * Dd, Y1);

        gemm_nt_bias<true ><<<dim3(DFF / 128, M / 128), 256>>>(M, DFF, Dd, Y1, w1, b1 + l * DFF, F);
        gemm_nt_bias<false><<<dim3(Dd / 128, M / 128), 256>>>(M, Dd, DFF, F, w2, b2 + l * Dd, Hb);

        float* outp = (l == LL - 1) ? (float*)d_out : X;
        add_ln_kernel<<<M, 256>>>(Y1, Hb, ln2g + l * Dd, ln2b + l * Dd, outp);
    }
}

// round 2
// speedup vs baseline: 2.5266x; 2.5266x over previous
#include <cuda_runtime.h>
#include <math.h>

#define Bb   8
#define Ss   1024
#define Dd   768
#define Hh   12
#define HDh  64
#define DFF  3072
#define LL   6

// ---------------- scratch ----------------
__device__ float gX [Bb*Ss*Dd];
__device__ float gQ [Bb*Ss*Dd];
__device__ float gK [Bb*Ss*Dd];
__device__ float gV [Bb*Ss*Dd];
__device__ float gS [100663296];         // B*H*S*S scores (402 MB)
__device__ float gHb[Bb*Ss*Dd];
__device__ float gY1[Bb*Ss*Dd];
__device__ float gF [Bb*Ss*DFF];

// ---------------- helpers ----------------
__device__ __forceinline__ unsigned f2tf32(float f) {
    unsigned u;
    asm("cvt.rna.tf32.f32 %0, %1;" : "=r"(u) : "f"(f));
    return u;
}

__device__ __forceinline__ void mma_tf32(float c[4], const unsigned a[4], const unsigned b[2]) {
    asm volatile(
        "mma.sync.aligned.m16n8k8.row.col.f32.tf32.tf32.f32 "
        "{%0,%1,%2,%3}, {%4,%5,%6,%7}, {%8,%9}, {%0,%1,%2,%3};\n"
        : "+f"(c[0]), "+f"(c[1]), "+f"(c[2]), "+f"(c[3])
        : "r"(a[0]), "r"(a[1]), "r"(a[2]), "r"(a[3]), "r"(b[0]), "r"(b[1]));
}

__device__ __forceinline__ float blockReduceSum(float v) {
    __shared__ float red[32];
    #pragma unroll
    for (int o = 16; o > 0; o >>= 1) v += __shfl_xor_sync(0xffffffffu, v, o);
    int lane = threadIdx.x & 31, w = threadIdx.x >> 5;
    if (lane == 0) red[w] = v;
    __syncthreads();
    v = (threadIdx.x < 8) ? red[threadIdx.x] : 0.f;
    if (w == 0) {
        #pragma unroll
        for (int o = 4; o > 0; o >>= 1) v += __shfl_xor_sync(0xffffffffu, v, o);
        if (lane == 0) red[0] = v;
    }
    __syncthreads();
    float r = red[0];
    __syncthreads();
    return r;
}

__device__ __forceinline__ float blockReduceMax(float v) {
    __shared__ float red[32];
    #pragma unroll
    for (int o = 16; o > 0; o >>= 1) v = fmaxf(v, __shfl_xor_sync(0xffffffffu, v, o));
    int lane = threadIdx.x & 31, w = threadIdx.x >> 5;
    if (lane == 0) red[w] = v;
    __syncthreads();
    v = (threadIdx.x < 8) ? red[threadIdx.x] : -3.4e38f;
    if (w == 0) {
        #pragma unroll
        for (int o = 4; o > 0; o >>= 1) v = fmaxf(v, __shfl_xor_sync(0xffffffffu, v, o));
        if (lane == 0) red[0] = v;
    }
    __syncthreads();
    float r = red[0];
    __syncthreads();
    return r;
}

// ---------------- embedding ----------------
__global__ void embed_kernel(const int* __restrict__ ids, const float* __restrict__ emb,
                             const float* __restrict__ pe, float* __restrict__ x) {
    int i  = blockIdx.x * blockDim.x + threadIdx.x;
    int d  = i % Dd;
    int bs = i / Dd;
    int s  = bs % Ss;
    x[i] = emb[(size_t)ids[bs] * Dd + d] + pe[(size_t)s * Dd + d];
}

// ---------------- TF32 NT GEMM: C = A[M,K] @ B[N,K]^T (*scale, +bias, relu) ----------------
// BM=128, BN=128, BK=32, 256 threads, warp tiles 64x32.
template<bool BIAS, bool RELU>
__global__ __launch_bounds__(256, 2) void gemm_tf32_nt(
    int M, int N, int K,
    const float* __restrict__ A, int lda, long az,
    const float* __restrict__ B, int ldb, long bz,
    float* __restrict__ C, int ldc, long cz,
    const float* __restrict__ bias, float scale)
{
    __shared__ unsigned As[128][36];
    __shared__ unsigned Bs[128][36];
    const int z = blockIdx.z;
    const float* Ap = A + (size_t)az * z + (size_t)(blockIdx.y * 128) * lda;
    const float* Bp = B + (size_t)bz * z + (size_t)(blockIdx.x * 128) * ldb;
    const int tid = threadIdx.x;
    const int lane = tid & 31, warp = tid >> 5;
    const int wm = (warp >> 2) * 64, wn = (warp & 3) * 32;
    const int grp = lane >> 2, tig = lane & 3;

    float acc[4][4][4] = {};

    for (int k0 = 0; k0 < K; k0 += 32) {
        #pragma unroll
        for (int p = 0; p < 4; p++) {
            int row = (tid >> 3) + p * 32;
            int c4 = (tid & 7) * 4;
            float4 a = *(const float4*)(Ap + (size_t)row * lda + k0 + c4);
            As[row][c4 + 0] = f2tf32(a.x); As[row][c4 + 1] = f2tf32(a.y);
            As[row][c4 + 2] = f2tf32(a.z); As[row][c4 + 3] = f2tf32(a.w);
            float4 b = *(const float4*)(Bp + (size_t)row * ldb + k0 + c4);
            Bs[row][c4 + 0] = f2tf32(b.x); Bs[row][c4 + 1] = f2tf32(b.y);
            Bs[row][c4 + 2] = f2tf32(b.z); Bs[row][c4 + 3] = f2tf32(b.w);
        }
        __syncthreads();
        #pragma unroll
        for (int kk = 0; kk < 4; kk++) {
            unsigned af[4][4], bf[4][2];
            #pragma unroll
            for (int mi = 0; mi < 4; mi++) {
                int r = wm + mi * 16 + grp;
                af[mi][0] = As[r][kk * 8 + tig];
                af[mi][1] = As[r + 8][kk * 8 + tig];
                af[mi][2] = As[r][kk * 8 + tig + 4];
                af[mi][3] = As[r + 8][kk * 8 + tig + 4];
            }
            #pragma unroll
            for (int ni = 0; ni < 4; ni++) {
                int nb = wn + ni * 8 + grp;
                bf[ni][0] = Bs[nb][kk * 8 + tig];
                bf[ni][1] = Bs[nb][kk * 8 + tig + 4];
            }
            #pragma unroll
            for (int mi = 0; mi < 4; mi++)
                #pragma unroll
                for (int ni = 0; ni < 4; ni++)
                    mma_tf32(acc[mi][ni], af[mi], bf[ni]);
        }
        __syncthreads();
    }

    float* Cp = C + (size_t)cz * z;
    #pragma unroll
    for (int mi = 0; mi < 4; mi++) {
        int row = blockIdx.y * 128 + wm + mi * 16 + grp;
        #pragma unroll
        for (int ni = 0; ni < 4; ni++) {
            int col = blockIdx.x * 128 + wn + ni * 8 + 2 * tig;
            float b0 = 0.f, b1 = 0.f;
            if (BIAS) { b0 = bias[col]; b1 = bias[col + 1]; }
            float v0 = acc[mi][ni][0] * scale + b0;
            float v1 = acc[mi][ni][1] * scale + b1;
            float v2 = acc[mi][ni][2] * scale + b0;
            float v3 = acc[mi][ni][3] * scale + b1;
            if (RELU) { v0 = fmaxf(v0, 0.f); v1 = fmaxf(v1, 0.f); v2 = fmaxf(v2, 0.f); v3 = fmaxf(v3, 0.f); }
            *(float2*)(Cp + (size_t)row * ldc + col)       = make_float2(v0, v1);
            *(float2*)(Cp + (size_t)(row + 8) * ldc + col) = make_float2(v2, v3);
        }
    }
}

// ---------------- TF32 NN GEMM for O = att @ V  (M=1024, N=64, K=1024 per bh) ----------------
// BM=128, BN=64, BK=32; warp tiles 64x16.
__global__ __launch_bounds__(256, 2) void gemm_av_tf32(
    const float* __restrict__ S, const float* __restrict__ V, float* __restrict__ O)
{
    __shared__ unsigned As[128][36];
    __shared__ unsigned Bs[32][72];
    const int z = blockIdx.z;
    const float* Ap = S + (size_t)z * Ss * Ss + (size_t)(blockIdx.y * 128) * Ss;
    const float* Bp = V + (size_t)z * Ss * HDh;
    const int tid = threadIdx.x;
    const int lane = tid & 31, warp = tid >> 5;
    const int wm = (warp >> 2) * 64, wn = (warp & 3) * 16;
    const int grp = lane >> 2, tig = lane & 3;

    float acc[4][2][4] = {};

    for (int k0 = 0; k0 < Ss; k0 += 32) {
        #pragma unroll
        for (int p = 0; p < 4; p++) {
            int row = (tid >> 3) + p * 32;
            int c4 = (tid & 7) * 4;
            float4 a = *(const float4*)(Ap + (size_t)row * Ss + k0 + c4);
            As[row][c4 + 0] = f2tf32(a.x); As[row][c4 + 1] = f2tf32(a.y);
            As[row][c4 + 2] = f2tf32(a.z); As[row][c4 + 3] = f2tf32(a.w);
        }
        #pragma unroll
        for (int p = 0; p < 2; p++) {
            int row = (tid >> 4) + p * 16;            // k within tile
            int c4 = (tid & 15) * 4;                  // n
            float4 b = *(const float4*)(Bp + (size_t)(k0 + row) * HDh + c4);
            Bs[row][c4 + 0] = f2tf32(b.x); Bs[row][c4 + 1] = f2tf32(b.y);
            Bs[row][c4 + 2] = f2tf32(b.z); Bs[row][c4 + 3] = f2tf32(b.w);
        }
        __syncthreads();
        #pragma unroll
        for (int kk = 0; kk < 4; kk++) {
            unsigned af[4][4], bf[2][2];
            #pragma unroll
            for (int mi = 0; mi < 4; mi++) {
                int r = wm + mi * 16 + grp;
                af[mi][0] = As[r][kk * 8 + tig];
                af[mi][1] = As[r + 8][kk * 8 + tig];
                af[mi][2] = As[r][kk * 8 + tig + 4];
                af[mi][3] = As[r + 8][kk * 8 + tig + 4];
            }
            #pragma unroll
            for (int ni = 0; ni < 2; ni++) {
                int nb = wn + ni * 8 + grp;
                bf[ni][0] = Bs[kk * 8 + tig][nb];
                bf[ni][1] = Bs[kk * 8 + tig + 4][nb];
            }
            #pragma unroll
            for (int mi = 0; mi < 4; mi++)
                #pragma unroll
                for (int ni = 0; ni < 2; ni++)
                    mma_tf32(acc[mi][ni], af[mi], bf[ni]);
        }
        __syncthreads();
    }

    const int b = z / Hh, h = z % Hh;
    float* Op = O + (size_t)b * Ss * Dd + (size_t)h * HDh;
    #pragma unroll
    for (int mi = 0; mi < 4; mi++) {
        int row = blockIdx.y * 128 + wm + mi * 16 + grp;
        #pragma unroll
        for (int ni = 0; ni < 2; ni++) {
            int col = wn + ni * 8 + 2 * tig;
            *(float2*)(Op + (size_t)row * Dd + col)       = make_float2(acc[mi][ni][0], acc[mi][ni][1]);
            *(float2*)(Op + (size_t)(row + 8) * Dd + col) = make_float2(acc[mi][ni][2], acc[mi][ni][3]);
        }
    }
}

// ---------------- softmax over rows of 1024 ----------------
__global__ __launch_bounds__(256) void softmax_kernel(float* __restrict__ Sb) {
    float* p = Sb + (size_t)blockIdx.x * Ss;
    float4 v = ((float4*)p)[threadIdx.x];
    float m = fmaxf(fmaxf(v.x, v.y), fmaxf(v.z, v.w));
    m = blockReduceMax(m);
    float e0 = __expf(v.x - m), e1 = __expf(v.y - m), e2 = __expf(v.z - m), e3 = __expf(v.w - m);
    float s = blockReduceSum(e0 + e1 + e2 + e3);
    float inv = 1.f / s;
    float4 o = {e0 * inv, e1 * inv, e2 * inv, e3 * inv};
    ((float4*)p)[threadIdx.x] = o;
}

// ---------------- add + layernorm ----------------
__global__ __launch_bounds__(256) void add_ln_kernel(
    const float* __restrict__ x, const float* __restrict__ h,
    const float* __restrict__ g, const float* __restrict__ bias, float* __restrict__ out)
{
    const size_t row = blockIdx.x;
    const float* px = x + row * Dd;
    const float* ph = h + row * Dd;
    int t = threadIdx.x;
    float v[3];
    #pragma unroll
    for (int i = 0; i < 3; i++) v[i] = px[t + i * 256] + ph[t + i * 256];
    float mu = blockReduceSum(v[0] + v[1] + v[2]) * (1.f / Dd);
    float q = 0.f;
    #pragma unroll
    for (int i = 0; i < 3; i++) { float d = v[i] - mu; q += d * d; }
    float var = blockReduceSum(q) * (1.f / Dd);
    float inv = rsqrtf(var + 1e-5f);
    float* po = out + row * Dd;
    #pragma unroll
    for (int i = 0; i < 3; i++) {
        int c = t + i * 256;
        po[c] = (v[i] - mu) * inv * g[c] + bias[c];
    }
}

// ---------------- host launcher ----------------
extern "C" void kernel_launch(void* const* d_in, const int* in_sizes, int n_in,
                              void* d_out, int out_size) {
    const int*   ids  = (const int*)  d_in[0];
    const float* emb  = (const float*)d_in[1];
    const float* pe   = (const float*)d_in[2];
    const float* Wq   = (const float*)d_in[3];
    const float* bq   = (const float*)d_in[4];
    const float* Wk   = (const float*)d_in[5];
    const float* bk   = (const float*)d_in[6];
    const float* Wv   = (const float*)d_in[7];
    const float* bv   = (const float*)d_in[8];
    const float* W1   = (const float*)d_in[9];
    const float* b1   = (const float*)d_in[10];
    const float* W2   = (const float*)d_in[11];
    const float* b2   = (const float*)d_in[12];
    const float* ln1g = (const float*)d_in[13];
    const float* ln1b = (const float*)d_in[14];
    const float* ln2g = (const float*)d_in[15];
    const float* ln2b = (const float*)d_in[16];

    float *X, *Q, *K, *V, *Sb, *Hb, *Y1, *F;
    cudaGetSymbolAddress((void**)&X,  gX);
    cudaGetSymbolAddress((void**)&Q,  gQ);
    cudaGetSymbolAddress((void**)&K,  gK);
    cudaGetSymbolAddress((void**)&V,  gV);
    cudaGetSymbolAddress((void**)&Sb, gS);
    cudaGetSymbolAddress((void**)&Hb, gHb);
    cudaGetSymbolAddress((void**)&Y1, gY1);
    cudaGetSymbolAddress((void**)&F,  gF);

    const int M = Bb * Ss;   // 8192

    embed_kernel<<<(Bb * Ss * Dd) / 256, 256>>>(ids, emb, pe, X);

    for (int l = 0; l < LL; l++) {
        const float* wq = Wq + (size_t)l * Dd * Dd;
        const float* wk = Wk + (size_t)l * Dd * Dd;
        const float* wv = Wv + (size_t)l * Dd * Dd;
        const float* w1 = W1 + (size_t)l * DFF * Dd;
        const float* w2 = W2 + (size_t)l * Dd * DFF;

        dim3 gQKV(Dd / 128, M / 128, 1);
        gemm_tf32_nt<true, false><<<gQKV, 256>>>(M, Dd, Dd, X, Dd, 0, wq, Dd, 0, Q, Dd, 0, bq + l * Dd, 1.f);
        gemm_tf32_nt<true, false><<<gQKV, 256>>>(M, Dd, Dd, X, Dd, 0, wk, Dd, 0, K, Dd, 0, bk + l * Dd, 1.f);
        gemm_tf32_nt<true, false><<<gQKV, 256>>>(M, Dd, Dd, X, Dd, 0, wv, Dd, 0, V, Dd, 0, bv + l * Dd, 1.f);

        // scores = Q @ K^T / 8 per (b,h)
        gemm_tf32_nt<false, false><<<dim3(Ss / 128, Ss / 128, Bb * Hh), 256>>>(
            Ss, Ss, HDh, Q, HDh, (long)Ss * HDh, K, HDh, (long)Ss * HDh,
            Sb, Ss, (long)Ss * Ss, nullptr, 0.125f);

        softmax_kernel<<<Bb * Hh * Ss, 256>>>(Sb);

        gemm_av_tf32<<<dim3(1, Ss / 128, Bb * Hh), 256>>>(Sb, V, Hb);

        add_ln_kernel<<<M, 256>>>(X, Hb, ln1g + l * Dd, ln1b + l * Dd, Y1);

        gemm_tf32_nt<true, true><<<dim3(DFF / 128, M / 128, 1), 256>>>(
            M, DFF, Dd, Y1, Dd, 0, w1, Dd, 0, F, DFF, 0, b1 + l * DFF, 1.f);
        gemm_tf32_nt<true, false><<<dim3(Dd / 128, M / 128, 1), 256>>>(
            M, Dd, DFF, F, DFF, 0, w2, DFF, 0, Hb, Dd, 0, b2 + l * Dd, 1.f);

        float* outp = (l == LL - 1) ? (float*)d_out : X;
        add_ln_kernel<<<M, 256>>>(Y1, Hb, ln2g + l * Dd, ln2b + l * Dd, outp);
    }
}